// round 17
// baseline (speedup 1.0000x reference)
#include <cuda_runtime.h>
#include <math.h>

// Problem constants (fixed by reference: R=32, G=32768, N=256, SH_DIM=9)
#define G_TOTAL 32768
#define NPTS    256
#define TPB     64
#define GPT     2     // gaussians per thread (packed f32x2)
#define PPB     32    // points per block -> grid (256, 8) = 2048 blocks

// SH normalization constants (degree 2, real basis)
#define C0  0.28209479177387814f
#define C1  0.4886025119029199f
#define C2A 0.5462742152960396f
#define C2B 0.15769578262626002f
#define C2C 0.2730689607973162f
#define NL2E (-1.4426950408889634f)   // -log2(e)

typedef unsigned long long u64;

__device__ __forceinline__ u64 pk2(float a, float b) {
    u64 r; asm("mov.b64 %0, {%1,%2};" : "=l"(r) : "f"(a), "f"(b)); return r;
}
__device__ __forceinline__ void unpk(u64 p, float& a, float& b) {
    asm("mov.b64 {%0,%1}, %2;" : "=f"(a), "=f"(b) : "l"(p));
}
__device__ __forceinline__ u64 f2fma(u64 a, u64 b, u64 c) {
    u64 r; asm("fma.rn.f32x2 %0, %1, %2, %3;" : "=l"(r) : "l"(a), "l"(b), "l"(c)); return r;
}
__device__ __forceinline__ u64 f2mul(u64 a, u64 b) {
    u64 r; asm("mul.rn.f32x2 %0, %1, %2;" : "=l"(r) : "l"(a), "l"(b)); return r;
}
__device__ __forceinline__ float rsq_approx(float x) {
    float r; asm("rsqrt.approx.f32 %0, %1;" : "=f"(r) : "f"(x)); return r;
}
__device__ __forceinline__ float ex2_approx(float x) {
    float r; asm("ex2.approx.f32 %0, %1;" : "=f"(r) : "f"(x)); return r;
}
__device__ __forceinline__ float rcp_approx(float x) {
    float r; asm("rcp.approx.f32 %0, %1;" : "=f"(r) : "f"(x)); return r;
}

__global__ __launch_bounds__(TPB) void gausssplat_kernel(
    const float* __restrict__ points,     // [N,3]
    const float* __restrict__ positions,  // [G,3]
    const float* __restrict__ scales,     // [G,3]
    const float4* __restrict__ rotations, // [G] float4 (16B aligned)
    const float* __restrict__ opacity,    // [G]
    const float* __restrict__ sh,         // [G,9]
    float* __restrict__ out)              // [N*G rgb][G sigma]
{
    const int g0    = (blockIdx.x * TPB + threadIdx.x) * GPT;
    const int nbase = blockIdx.y * PPB;

    // Broadcast-duplicated point rows: {x,x,y,y,z,z,_,_} (32B stride)
    __shared__ float sp[PPB][8];
    if (threadIdx.x < PPB) {
        const int n = nbase + threadIdx.x;
        const float x = points[3*n + 0] * 0.25f;
        const float y = points[3*n + 1] * 0.25f;
        const float z = points[3*n + 2] * 0.25f;
        sp[threadIdx.x][0] = x; sp[threadIdx.x][1] = x;
        sp[threadIdx.x][2] = y; sp[threadIdx.x][3] = y;
        sp[threadIdx.x][4] = z; sp[threadIdx.x][5] = z;
    }
    __syncthreads();

    // ---- Per-gaussian precompute (scalar), packed into f32x2 constants ----
    float m00[2], m01[2], m02[2], m10[2], m11[2], m12[2], m20[2], m21[2], m22[2];
    float ncx[2], ncy[2], ncz[2];
    float c1y[2], c1z[2], c1x[2], cxy[2], cyz[2], cxz[2], c8[2], c63[2], cb[2];

    #pragma unroll
    for (int k = 0; k < GPT; ++k) {
        const int g = g0 + k;
        const float isx = rcp_approx(scales[3*g + 0] + 1e-6f);
        const float isy = rcp_approx(scales[3*g + 1] + 1e-6f);
        const float isz = rcp_approx(scales[3*g + 2] + 1e-6f);

        const float4 qv = rotations[g];
        const float q0 = qv.x, q1 = qv.y, q2 = qv.z, q3 = qv.w;

        // M = R * diag(1/s)  (quat->matrix without normalization, as reference)
        m00[k] = (1.0f - 2.0f*(q2*q2 + q3*q3)) * isx;
        m01[k] = (2.0f*(q1*q2 - q0*q3))        * isy;
        m02[k] = (2.0f*(q1*q3 + q0*q2))        * isz;
        m10[k] = (2.0f*(q1*q2 + q0*q3))        * isx;
        m11[k] = (1.0f - 2.0f*(q1*q1 + q3*q3)) * isy;
        m12[k] = (2.0f*(q2*q3 - q0*q1))        * isz;
        m20[k] = (2.0f*(q1*q3 - q0*q2))        * isx;
        m21[k] = (2.0f*(q2*q3 + q0*q1))        * isy;
        m22[k] = (1.0f - 2.0f*(q1*q1 + q2*q2)) * isz;

        const float px = positions[3*g + 0];
        const float py = positions[3*g + 1];
        const float pz = positions[3*g + 2];
        ncx[k] = -(m00[k]*px + m01[k]*py + m02[k]*pz);
        ncy[k] = -(m10[k]*px + m11[k]*py + m12[k]*pz);
        ncz[k] = -(m20[k]*px + m21[k]*py + m22[k]*pz);

        // Fold SH norm constants AND -log2(e) (ex2 sigmoid) into coefficients
        c1y[k] = sh[9*g + 1] * (C1 * NL2E);
        c1z[k] = sh[9*g + 2] * (C1 * NL2E);
        c1x[k] = sh[9*g + 3] * (C1 * NL2E);
        cxy[k] = sh[9*g + 4] * (C2A * NL2E);
        cyz[k] = sh[9*g + 5] * (C2A * NL2E);
        c63[k] = sh[9*g + 6] * (3.0f * C2B * NL2E);
        cxz[k] = sh[9*g + 7] * (C2A * NL2E);
        c8[k]  = sh[9*g + 8] * (C2C * NL2E);
        cb[k]  = (sh[9*g + 0] * C0 - sh[9*g + 6] * C2B) * NL2E;
    }

    const u64 M00 = pk2(m00[0], m00[1]), M01 = pk2(m01[0], m01[1]), M02 = pk2(m02[0], m02[1]);
    const u64 M10 = pk2(m10[0], m10[1]), M11 = pk2(m11[0], m11[1]), M12 = pk2(m12[0], m12[1]);
    const u64 M20 = pk2(m20[0], m20[1]), M21 = pk2(m21[0], m21[1]), M22 = pk2(m22[0], m22[1]);
    const u64 NCX = pk2(ncx[0], ncx[1]), NCY = pk2(ncy[0], ncy[1]), NCZ = pk2(ncz[0], ncz[1]);
    const u64 S1  = pk2(c1y[0], c1y[1]), S2  = pk2(c1z[0], c1z[1]), S3  = pk2(c1x[0], c1x[1]);
    const u64 S4  = pk2(cxy[0], cxy[1]), S5  = pk2(cyz[0], cyz[1]), S7  = pk2(cxz[0], cxz[1]);
    const u64 S8  = pk2(c8[0],  c8[1]),  NS8 = pk2(-c8[0], -c8[1]);
    const u64 S63 = pk2(c63[0], c63[1]), BSE = pk2(cb[0],  cb[1]);

    // sigma = softplus(opacity) once
    if (blockIdx.y == 0) {
        float2 sg;
        const float o0 = opacity[g0];
        const float o1 = opacity[g0 + 1];
        sg.x = fmaxf(o0, 0.0f) + log1pf(__expf(-fabsf(o0)));
        sg.y = fmaxf(o1, 0.0f) + log1pf(__expf(-fabsf(o1)));
        *(float2*)(out + (size_t)NPTS * G_TOTAL + g0) = sg;
    }

    float* __restrict__ orow = out + (size_t)nbase * G_TOTAL + g0;

    #pragma unroll
    for (int i = 0; i < PPB; ++i) {
        const u64 PX = *(const u64*)&sp[i][0];
        const u64 PY = *(const u64*)&sp[i][2];
        const u64 PZ = *(const u64*)&sp[i][4];

        // rotated+scaled diff: M*p - c  (9 packed FMA)
        const u64 rx = f2fma(M00, PX, f2fma(M01, PY, f2fma(M02, PZ, NCX)));
        const u64 ry = f2fma(M10, PX, f2fma(M11, PY, f2fma(M12, PZ, NCY)));
        const u64 rz = f2fma(M20, PX, f2fma(M21, PY, f2fma(M22, PZ, NCZ)));

        const u64 zz = f2mul(rz, rz);
        const u64 n2 = f2fma(rx, rx, f2fma(ry, ry, zz));

        float n2a, n2b; unpk(n2, n2a, n2b);
        const u64 inv = pk2(rsq_approx(n2a), rsq_approx(n2b));

        // degree-1 (unnormalized)
        const u64 lin = f2fma(S1, ry, f2fma(S2, rz, f2mul(S3, rx)));
        // degree-2 (unnormalized, Horner): x(s8x+s4y+s7z) + y(s5z-s8y) + s63 z^2
        const u64 t1 = f2fma(S8, rx, f2fma(S4, ry, f2mul(S7, rz)));
        const u64 t2 = f2fma(NS8, ry, f2mul(S5, rz));
        const u64 q  = f2fma(rx, t1, f2fma(ry, t2, f2mul(S63, zz)));

        // v' = ((q*inv + lin)*inv + bse)   [-log2e folded into coefficients]
        const u64 v = f2fma(f2fma(q, inv, lin), inv, BSE);

        float va, vb; unpk(v, va, vb);
        float2 res;
        res.x = rcp_approx(1.0f + ex2_approx(va));
        res.y = rcp_approx(1.0f + ex2_approx(vb));

        *(float2*)&orow[(size_t)i * G_TOTAL] = res;
    }
}

extern "C" void kernel_launch(void* const* d_in, const int* in_sizes, int n_in,
                              void* d_out, int out_size) {
    const float* points    = (const float*)d_in[0];
    const float* positions = (const float*)d_in[1];
    const float* scales    = (const float*)d_in[2];
    const float4* rotations= (const float4*)d_in[3];
    const float* opacity   = (const float*)d_in[4];
    const float* sh        = (const float*)d_in[5];
    float* out = (float*)d_out;

    dim3 grid(G_TOTAL / (TPB * GPT), NPTS / PPB);
    gausssplat_kernel<<<grid, TPB>>>(points, positions, scales, rotations,
                                     opacity, sh, out);
}